// round 1
// baseline (speedup 1.0000x reference)
#include <cuda_runtime.h>
#include <cstdint>

// PositionEncoding: out[b,s,d] = x[b,s,d] + pe[s,d]
//   pe[s,d] = sin(s / 10000^(d/D)) if d even else cos(s / 10000^(d/D))
// Shapes: B=8, S=4096, D=1024 (fp32).
//
// Strategy: one thread per (s, d4) float4 of the PE row; compute the 4 PE
// values in registers (2 sin + 2 cos), then stream all 8 batches with
// vectorized float4 load/add/store. No PE table in memory -> pure 2x-stream
// HBM-bound kernel (read x once, write out once).

static constexpr int B = 8;
static constexpr int S = 4096;
static constexpr int D = 1024;
static constexpr int D4 = D / 4;                 // 256 float4 per row
static constexpr int SD4 = S * D4;               // 1,048,576 threads' worth
static constexpr long long BATCH_STRIDE4 = (long long)S * D4;  // float4 units

// log2(10000) / D  (D = 1024)
static constexpr float LOG2_10000_OVER_D = 13.287712379549449f / 1024.0f;

__global__ __launch_bounds__(256)
void pe_add_kernel(const float4* __restrict__ x, float4* __restrict__ out) {
    int idx = blockIdx.x * blockDim.x + threadIdx.x;
    if (idx >= SD4) return;

    int s  = idx >> 8;          // idx / D4   (D4 = 256)
    int d4 = idx & (D4 - 1);    // idx % D4
    int d  = d4 << 2;

    float fs = (float)s;

    // inv_wave_j = 10000^(-(d+j)/D) = exp2(-(d+j) * log2(10000)/D)
    float a0 = fs * exp2f(-(float)(d + 0) * LOG2_10000_OVER_D);
    float a1 = fs * exp2f(-(float)(d + 1) * LOG2_10000_OVER_D);
    float a2 = fs * exp2f(-(float)(d + 2) * LOG2_10000_OVER_D);
    float a3 = fs * exp2f(-(float)(d + 3) * LOG2_10000_OVER_D);

    float4 pe;
    pe.x = sinf(a0);   // d even -> sin
    pe.y = cosf(a1);   // d odd  -> cos
    pe.z = sinf(a2);
    pe.w = cosf(a3);

    long long base = idx;
#pragma unroll
    for (int b = 0; b < B; b++) {
        long long off = base + (long long)b * BATCH_STRIDE4;
        float4 v = x[off];
        v.x += pe.x;
        v.y += pe.y;
        v.z += pe.z;
        v.w += pe.w;
        out[off] = v;
    }
}

extern "C" void kernel_launch(void* const* d_in, const int* in_sizes, int n_in,
                              void* d_out, int out_size) {
    const float4* x = (const float4*)d_in[0];
    float4* out = (float4*)d_out;

    int threads = 256;
    int blocks = (SD4 + threads - 1) / threads;   // 4096 blocks
    pe_add_kernel<<<blocks, threads>>>(x, out);
}

// round 2
// speedup vs baseline: 1.0456x; 1.0456x over previous
#include <cuda_runtime.h>
#include <cstdint>

// PositionEncoding: out[b,s,d] = x[b,s,d] + pe[s,d]
//   pe[s,d] = sin(s / 10000^(d/D)) if d even else cos(s / 10000^(d/D))
// Shapes: B=8, S=4096, D=1024 (fp32).
//
// R2: front-batch all 8 batch loads (MLP=8), compute trig while loads are in
// flight, then add+store all 8. Avoids fine-grain read/write interleave and
// hides trig entirely under memory latency.

static constexpr int B = 8;
static constexpr int S = 4096;
static constexpr int D = 1024;
static constexpr int D4 = D / 4;                  // 256 float4 per row
static constexpr int SD4 = S * D4;                // 1,048,576
static constexpr long long BATCH_STRIDE4 = (long long)S * D4;

// log2(10000) / D  (D = 1024)
static constexpr float LOG2_10000_OVER_D = 13.287712379549449f / 1024.0f;

__global__ __launch_bounds__(256)
void pe_add_kernel(const float4* __restrict__ x, float4* __restrict__ out) {
    int idx = blockIdx.x * blockDim.x + threadIdx.x;   // grid exactly covers SD4

    // ---- issue all 8 loads first (front-batched LDG.128, MLP=8) ----
    float4 v[B];
#pragma unroll
    for (int b = 0; b < B; b++) {
        v[b] = __ldcg(&x[idx + (long long)b * BATCH_STRIDE4]);
    }

    // ---- compute PE while the loads are in flight ----
    int s  = idx >> 8;          // idx / D4
    int d4 = idx & (D4 - 1);    // idx % D4
    int d  = d4 << 2;
    float fs = (float)s;

    float a0 = fs * exp2f(-(float)(d + 0) * LOG2_10000_OVER_D);
    float a1 = fs * exp2f(-(float)(d + 1) * LOG2_10000_OVER_D);
    float a2 = fs * exp2f(-(float)(d + 2) * LOG2_10000_OVER_D);
    float a3 = fs * exp2f(-(float)(d + 3) * LOG2_10000_OVER_D);

    float pex = sinf(a0);   // even dim -> sin
    float pey = cosf(a1);   // odd dim  -> cos
    float pez = sinf(a2);
    float pew = cosf(a3);

    // ---- add + store all 8 ----
#pragma unroll
    for (int b = 0; b < B; b++) {
        float4 o;
        o.x = v[b].x + pex;
        o.y = v[b].y + pey;
        o.z = v[b].z + pez;
        o.w = v[b].w + pew;
        __stcg(&out[idx + (long long)b * BATCH_STRIDE4], o);
    }
}

extern "C" void kernel_launch(void* const* d_in, const int* in_sizes, int n_in,
                              void* d_out, int out_size) {
    const float4* x = (const float4*)d_in[0];
    float4* out = (float4*)d_out;

    int threads = 256;
    int blocks = SD4 / threads;   // 4096, exact
    pe_add_kernel<<<blocks, threads>>>(x, out);
}